// round 5
// baseline (speedup 1.0000x reference)
#include <cuda_runtime.h>
#include <cstdint>

// Problem constants (fixed by the reference)
#define N_CLASSES 50000
#define EMBED_DIM 128
#define N_TOKENS  2048

#define TPB   256                 // threads per block
#define VPT   8                   // float4 vectors per thread per iteration
#define CHUNK (TPB * VPT)         // 2048 float4 per chunk
// total float4: N_CLASSES*N_TOKENS/4 = 25,600,000 -> 12,500 chunks
#define NCHUNKS (N_CLASSES * (N_TOKENS / 4) / CHUNK)
#define GRID  592                 // 4 CTAs/SM x 148 SMs: fully resident, 1 wave

// ---------------------------------------------------------------------------
// Rare path: token n's class is c -> gather its 128-dim embedding.
//   out[n, d] = lookup[d * N_CLASSES + c],  d = 0..127
// 128 independent scattered loads (unroll 8 -> 32 in flight), coalesced
// float4 stores. Hidden under the surrounding DRAM stream.
// ---------------------------------------------------------------------------
__device__ __forceinline__ void gather_token(
    const float* __restrict__ lookup, float* __restrict__ out, int c, int n)
{
    const float* __restrict__ src = lookup + c;
    float4* __restrict__ dst = reinterpret_cast<float4*>(out + n * EMBED_DIM);
    #pragma unroll 8
    for (int j = 0; j < EMBED_DIM / 4; ++j) {
        float4 r;
        r.x = src[(size_t)(4 * j + 0) * N_CLASSES];
        r.y = src[(size_t)(4 * j + 1) * N_CLASSES];
        r.z = src[(size_t)(4 * j + 2) * N_CLASSES];
        r.w = src[(size_t)(4 * j + 3) * N_CLASSES];
        dst[j] = r;
    }
}

// ---------------------------------------------------------------------------
// Persistent fused scan + gather over the dense one-hot matrix
// [N_CLASSES, N_TOKENS] (row-major fp32). 592 resident CTAs grid-stride over
// 12,500 chunks; each thread streams 8 float4s per iteration (blockDim-
// strided, coalesced, evict-first). On the rare nonzero hit, the finder
// thread gathers that token's embedding directly. Integer compare vs 0 is
// exact: one_hot yields only 0.0f (0x00000000) and 1.0f, never -0.0.
// ---------------------------------------------------------------------------
__global__ void __launch_bounds__(TPB) onehot_embed_persistent_kernel(
    const uint4* __restrict__ types_v4,
    const float* __restrict__ lookup,
    float*       __restrict__ out)
{
    const unsigned int tid = threadIdx.x;

    for (unsigned int chunk = blockIdx.x; chunk < NCHUNKS; chunk += gridDim.x) {
        const unsigned int base = chunk * CHUNK + tid;

        uint4 v[VPT];
        #pragma unroll
        for (int u = 0; u < VPT; ++u)
            v[u] = __ldcs(&types_v4[base + u * TPB]);

        unsigned int any = 0;
        #pragma unroll
        for (int u = 0; u < VPT; ++u)
            any |= v[u].x | v[u].y | v[u].z | v[u].w;

        if (any != 0u) {                          // rare: ~2048 hits total
            #pragma unroll
            for (int u = 0; u < VPT; ++u) {
                if ((v[u].x | v[u].y | v[u].z | v[u].w) != 0u) {
                    const unsigned int i = base + u * TPB;  // float4 index
                    const int c = (int)(i >> 9);            // class row (512 f4/row)
                    const int n = (int)(i & 511u) << 2;     // token col base
                    if (v[u].x) gather_token(lookup, out, c, n + 0);
                    if (v[u].y) gather_token(lookup, out, c, n + 1);
                    if (v[u].z) gather_token(lookup, out, c, n + 2);
                    if (v[u].w) gather_token(lookup, out, c, n + 3);
                }
            }
        }
    }
}

extern "C" void kernel_launch(void* const* d_in, const int* in_sizes, int n_in,
                              void* d_out, int out_size)
{
    // Resolve inputs by size: types has 102,400,000 elems, lookup 6,400,000.
    const float* types  = (const float*)d_in[0];
    const float* lookup = (const float*)d_in[1];
    if (n_in >= 2 && in_sizes[0] == EMBED_DIM * N_CLASSES &&
        in_sizes[1] == N_CLASSES * N_TOKENS) {
        const float* t = types; types = lookup; lookup = t;
    }

    onehot_embed_persistent_kernel<<<GRID, TPB>>>(
        (const uint4*)types, lookup, (float*)d_out);
}

// round 6
// speedup vs baseline: 1.0110x; 1.0110x over previous
#include <cuda_runtime.h>
#include <cstdint>

// Problem constants (fixed by the reference)
#define N_CLASSES 50000
#define EMBED_DIM 128
#define N_TOKENS  2048

#define TPB   256                 // threads per block
#define VPT   8                   // float4 vectors per thread per chunk
#define CHUNK (TPB * VPT)         // 2048 float4 per chunk
// total float4: N_CLASSES*N_TOKENS/4 = 25,600,000 -> 12,500 chunks
#define NCHUNKS (N_CLASSES * (N_TOKENS / 4) / CHUNK)
#define GRID  1184                // 8 CTAs/SM x 148 SMs: full residency, 1 wave

// ---------------------------------------------------------------------------
// Rare path: token n's class is c -> gather its 128-dim embedding.
//   out[n, d] = lookup[d * N_CLASSES + c],  d = 0..127
// ---------------------------------------------------------------------------
__device__ __forceinline__ void gather_token(
    const float* __restrict__ lookup, float* __restrict__ out, int c, int n)
{
    const float* __restrict__ src = lookup + c;
    float4* __restrict__ dst = reinterpret_cast<float4*>(out + n * EMBED_DIM);
    #pragma unroll 8
    for (int j = 0; j < EMBED_DIM / 4; ++j) {
        float4 r;
        r.x = src[(size_t)(4 * j + 0) * N_CLASSES];
        r.y = src[(size_t)(4 * j + 1) * N_CLASSES];
        r.z = src[(size_t)(4 * j + 2) * N_CLASSES];
        r.w = src[(size_t)(4 * j + 3) * N_CLASSES];
        dst[j] = r;
    }
}

// Front-batched load of one chunk's 8 float4s (coalesced, evict-first).
__device__ __forceinline__ void load_chunk(
    uint4 (&v)[VPT], const uint4* __restrict__ types_v4,
    unsigned int chunk, unsigned int tid)
{
    const unsigned int base = chunk * CHUNK + tid;
    #pragma unroll
    for (int u = 0; u < VPT; ++u)
        v[u] = __ldcs(&types_v4[base + u * TPB]);
}

// OR-test + rare gather for one loaded chunk. Integer compare vs 0 is exact:
// one_hot yields only 0.0f (0x00000000) and 1.0f, never -0.0.
__device__ __forceinline__ void process_chunk(
    const uint4 (&v)[VPT], const float* __restrict__ lookup,
    float* __restrict__ out, unsigned int chunk, unsigned int tid)
{
    unsigned int any = 0;
    #pragma unroll
    for (int u = 0; u < VPT; ++u)
        any |= v[u].x | v[u].y | v[u].z | v[u].w;

    if (any != 0u) {                              // rare: ~2048 hits total
        const unsigned int base = chunk * CHUNK + tid;
        #pragma unroll
        for (int u = 0; u < VPT; ++u) {
            if ((v[u].x | v[u].y | v[u].z | v[u].w) != 0u) {
                const unsigned int i = base + u * TPB;  // float4 index
                const int c = (int)(i >> 9);            // class row (512 f4/row)
                const int n = (int)(i & 511u) << 2;     // token col base
                if (v[u].x) gather_token(lookup, out, c, n + 0);
                if (v[u].y) gather_token(lookup, out, c, n + 1);
                if (v[u].z) gather_token(lookup, out, c, n + 2);
                if (v[u].w) gather_token(lookup, out, c, n + 3);
            }
        }
    }
}

// ---------------------------------------------------------------------------
// Persistent, 2-deep software-pipelined scan+gather. 1184 resident CTAs
// (8/SM) grid-stride over 12,500 chunks. The next chunk's loads are issued
// BEFORE the current chunk's OR-test consumes its data, so each warp keeps
// >=8 LDG.128 in flight across every iteration boundary (no MLP drain).
// Alternating A/B register buffers -> no per-iteration register copies.
// ---------------------------------------------------------------------------
__global__ void __launch_bounds__(TPB) onehot_embed_pipelined_kernel(
    const uint4* __restrict__ types_v4,
    const float* __restrict__ lookup,
    float*       __restrict__ out)
{
    const unsigned int tid = threadIdx.x;

    unsigned int c0 = blockIdx.x;                 // always < NCHUNKS (1184<12500)
    uint4 A[VPT], B[VPT];
    load_chunk(A, types_v4, c0, tid);

    while (true) {
        const unsigned int c1 = c0 + GRID;
        const bool hb = (c1 < NCHUNKS);
        if (hb) load_chunk(B, types_v4, c1, tid); // prefetch before consuming A
        process_chunk(A, lookup, out, c0, tid);
        if (!hb) break;

        const unsigned int c2 = c1 + GRID;
        const bool ha = (c2 < NCHUNKS);
        if (ha) load_chunk(A, types_v4, c2, tid); // prefetch before consuming B
        process_chunk(B, lookup, out, c1, tid);
        if (!ha) break;

        c0 = c2;
    }
}

extern "C" void kernel_launch(void* const* d_in, const int* in_sizes, int n_in,
                              void* d_out, int out_size)
{
    // Resolve inputs by size: types has 102,400,000 elems, lookup 6,400,000.
    const float* types  = (const float*)d_in[0];
    const float* lookup = (const float*)d_in[1];
    if (n_in >= 2 && in_sizes[0] == EMBED_DIM * N_CLASSES &&
        in_sizes[1] == N_CLASSES * N_TOKENS) {
        const float* t = types; types = lookup; lookup = t;
    }

    onehot_embed_pipelined_kernel<<<GRID, TPB>>>(
        (const uint4*)types, lookup, (float*)d_out);
}

// round 7
// speedup vs baseline: 1.1093x; 1.0972x over previous
#include <cuda_runtime.h>
#include <cstdint>

// Problem constants (fixed by the reference)
#define N_CLASSES 50000
#define EMBED_DIM 128
#define N_TOKENS  2048

#define TPB   256                 // threads per block
#define VPT   16                  // float4 vectors per thread
// total float4: N_CLASSES*N_TOKENS/4 = 25,600,000 = 6,250 blocks * 256 * 16
#define NBLOCKS (N_CLASSES * (N_TOKENS / 4) / (TPB * VPT))

// ---------------------------------------------------------------------------
// Rare path: token n's class is c -> gather its 128-dim embedding.
//   out[n, d] = lookup[d * N_CLASSES + c],  d = 0..127
// 128 independent scattered loads (unroll 8 -> 32 in flight), coalesced
// float4 stores. Hidden under the surrounding DRAM stream.
// ---------------------------------------------------------------------------
__device__ __forceinline__ void gather_token(
    const float* __restrict__ lookup, float* __restrict__ out, int c, int n)
{
    const float* __restrict__ src = lookup + c;
    float4* __restrict__ dst = reinterpret_cast<float4*>(out + n * EMBED_DIM);
    #pragma unroll 8
    for (int j = 0; j < EMBED_DIM / 4; ++j) {
        float4 r;
        r.x = src[(size_t)(4 * j + 0) * N_CLASSES];
        r.y = src[(size_t)(4 * j + 1) * N_CLASSES];
        r.z = src[(size_t)(4 * j + 2) * N_CLASSES];
        r.w = src[(size_t)(4 * j + 3) * N_CLASSES];
        dst[j] = r;
    }
}

// ---------------------------------------------------------------------------
// Fused scan + gather over the dense one-hot matrix [N_CLASSES, N_TOKENS]
// (row-major fp32). Non-persistent: 6,250 short-lived CTAs, HW backfill.
// Each thread front-batches 16 float4 loads (blockDim-strided, coalesced,
// evict-first) -> ~16 LDG.128 in flight per thread. On the rare nonzero hit,
// the finder thread gathers that token's embedding directly. Integer compare
// vs 0 is exact: one_hot yields only 0.0f (0x00000000) and 1.0f, never -0.0.
// ---------------------------------------------------------------------------
__global__ void __launch_bounds__(TPB) onehot_embed_fused_kernel(
    const uint4* __restrict__ types_v4,
    const float* __restrict__ lookup,
    float*       __restrict__ out)
{
    const unsigned int base = blockIdx.x * (TPB * VPT) + threadIdx.x;

    uint4 v[VPT];
    #pragma unroll
    for (int u = 0; u < VPT; ++u)
        v[u] = __ldcs(&types_v4[base + u * TPB]);

    unsigned int any = 0;
    #pragma unroll
    for (int u = 0; u < VPT; ++u)
        any |= v[u].x | v[u].y | v[u].z | v[u].w;

    if (any != 0u) {                              // rare: ~2048 / 1.6M threads
        #pragma unroll
        for (int u = 0; u < VPT; ++u) {
            if ((v[u].x | v[u].y | v[u].z | v[u].w) != 0u) {
                const unsigned int i = base + u * TPB;   // float4 index
                const int c = (int)(i >> 9);             // class row (512 f4/row)
                const int n = (int)(i & 511u) << 2;      // token col base
                if (v[u].x) gather_token(lookup, out, c, n + 0);
                if (v[u].y) gather_token(lookup, out, c, n + 1);
                if (v[u].z) gather_token(lookup, out, c, n + 2);
                if (v[u].w) gather_token(lookup, out, c, n + 3);
            }
        }
    }
}

extern "C" void kernel_launch(void* const* d_in, const int* in_sizes, int n_in,
                              void* d_out, int out_size)
{
    // Resolve inputs by size: types has 102,400,000 elems, lookup 6,400,000.
    const float* types  = (const float*)d_in[0];
    const float* lookup = (const float*)d_in[1];
    if (n_in >= 2 && in_sizes[0] == EMBED_DIM * N_CLASSES &&
        in_sizes[1] == N_CLASSES * N_TOKENS) {
        const float* t = types; types = lookup; lookup = t;
    }

    onehot_embed_fused_kernel<<<NBLOCKS, TPB>>>(
        (const uint4*)types, lookup, (float*)d_out);
}